// round 15
// baseline (speedup 1.0000x reference)
#include <cuda_runtime.h>
#include <cuda_fp16.h>
#include <cstdint>

// Problem constants
#define BSZ  4
#define TLEN 2048
#define CDIM 1024
#define HN   16
#define DD   64
#define MROWS (BSZ * TLEN)   // 8192

// ---------------------------------------------------------------------------
// fp16 planes (device-global scratch; allocation-free)
// ---------------------------------------------------------------------------
__device__ __half g_xr[MROWS * CDIM];                      // x rounded
__device__ __half g_wq[CDIM * CDIM], g_wk[CDIM * CDIM];
__device__ __half g_wv[CDIM * CDIM], g_wp[CDIM * CDIM];
__device__ __half g_qr[MROWS * CDIM];                      // Q rounded (log2e-scaled)
__device__ __half g_kh[MROWS * CDIM];                      // K rounded
__device__ __half g_vh[MROWS * CDIM];                      // V rounded
__device__ __half g_yr[MROWS * CDIM];                      // Y rounded [B,T,C]

// ===========================================================================
// Helpers
// ===========================================================================
__device__ __forceinline__ uint32_t smem_u32(const void* p) {
    uint32_t a;
    asm("{ .reg .u64 t; cvta.to.shared.u64 t, %1; cvt.u32.u64 %0, t; }"
        : "=r"(a) : "l"(p));
    return a;
}

__device__ __forceinline__ void ldsm4(uint32_t* r, uint32_t addr) {
    asm volatile("ldmatrix.sync.aligned.m8n8.x4.shared.b16 {%0,%1,%2,%3}, [%4];"
        : "=r"(r[0]), "=r"(r[1]), "=r"(r[2]), "=r"(r[3]) : "r"(addr));
}

__device__ __forceinline__ void ldsm4t(uint32_t* r, uint32_t addr) {
    asm volatile("ldmatrix.sync.aligned.m8n8.x4.trans.shared.b16 {%0,%1,%2,%3}, [%4];"
        : "=r"(r[0]), "=r"(r[1]), "=r"(r[2]), "=r"(r[3]) : "r"(addr));
}

__device__ __forceinline__ void mma16816(float* c, const uint32_t* a,
                                         const uint32_t* b) {
    asm volatile(
        "mma.sync.aligned.m16n8k16.row.col.f32.f16.f16.f32 "
        "{%0,%1,%2,%3}, {%4,%5,%6,%7}, {%8,%9}, {%0,%1,%2,%3};"
        : "+f"(c[0]), "+f"(c[1]), "+f"(c[2]), "+f"(c[3])
        : "r"(a[0]), "r"(a[1]), "r"(a[2]), "r"(a[3]), "r"(b[0]), "r"(b[1]));
}

__device__ __forceinline__ uint32_t round2(float a, float b) {
    __half2 h = __floats2half2_rn(a, b);
    return *reinterpret_cast<uint32_t*>(&h);
}

// exp2 on a packed half2 (MUFU, 2 values per op)
__device__ __forceinline__ uint32_t ex2h2(uint32_t x) {
    uint32_t y;
    asm("ex2.approx.f16x2 %0, %1;" : "=r"(y) : "r"(x));
    return y;
}

__device__ __forceinline__ void cp_async16(uint32_t dst, const void* src) {
    asm volatile("cp.async.cg.shared.global [%0], [%1], 16;" :: "r"(dst), "l"(src));
}
#define CP_COMMIT() asm volatile("cp.async.commit_group;" ::: "memory")
#define CP_WAIT(n)  asm volatile("cp.async.wait_group %0;" :: "n"(n) : "memory")

// ===========================================================================
// Prep: round fp32 -> fp16.
// ===========================================================================
__global__ __launch_bounds__(256)
void round_fp32(const float* __restrict__ src, __half* __restrict__ dst)
{
    const int i = (blockIdx.x * 256 + threadIdx.x) * 4;
    const float4 v = *reinterpret_cast<const float4*>(src + i);
    *reinterpret_cast<uint2*>(dst + i) =
        make_uint2(round2(v.x, v.y), round2(v.z, v.w));
}

struct W4Args { const float* s0; const float* s1; const float* s2; const float* s3;
                __half* d0; __half* d1; __half* d2; __half* d3; };

__global__ __launch_bounds__(256)
void round_w4(W4Args a)
{
    const int g = blockIdx.y;
    const float* s = (g == 0) ? a.s0 : (g == 1) ? a.s1 : (g == 2) ? a.s2 : a.s3;
    __half* d      = (g == 0) ? a.d0 : (g == 1) ? a.d1 : (g == 2) ? a.d2 : a.d3;
    const int i = (blockIdx.x * 256 + threadIdx.x) * 4;
    const float4 v = *reinterpret_cast<const float4*>(s + i);
    *reinterpret_cast<uint2*>(d + i) =
        make_uint2(round2(v.x, v.y), round2(v.z, v.w));
}

// ===========================================================================
// GEMM skeleton: out = (A @ W^T + bias) * scale, fp16 1-term.
// CTA 128x128, K-tile 64, 3-stage cp.async ring, 256 threads,
// 8 warps (4M x 2N), warp tile 32x64. 2 CTAs/SM. Persistent CTAs.
// ks-loop fragment ping-pong: frags[ks+1] loaded during MMA[ks].
// ===========================================================================
#define NKT 16                        // 1024 / 64
#define STAGE_BYTES 32768             // A,B each 128*128B = 16 KB
#define OFF_AH 0
#define OFF_BH 16384
#define GEMM_SMEM (3 * STAGE_BYTES)   // 96 KB
#define PGRID 296                     // 148 SMs x 2 CTAs
#define QKV_TILES (3 * (CDIM / 128) * (MROWS / 128))   // 1536
#define PROJ_TILES ((CDIM / 128) * (MROWS / 128))      // 512

struct QKVArgs {
    const __half *W0, *W1, *W2;
    const float *b0, *b1, *b2;
    __half *o0, *o1, *o2;             // rounded single plane each
};

__device__ __forceinline__ void gemm_mainloop(
    const __half* __restrict__ Ar, const __half* __restrict__ Wr,
    int m0, int n0, uint32_t sbase, float acc[2][8][4])
{
    const int tid  = threadIdx.x;
    const int lane = tid & 31;
    const int wid  = tid >> 5;
    const int m_off = (wid & 3) * 32;
    const int n_off = (wid >> 2) * 64;

    const int a_row_l = ((lane >> 3) & 1) * 8 + (lane & 7);
    const int a_chunk = lane >> 4;
    const int b_row_l = ((lane >> 4) & 1) * 8 + (lane & 7);
    const int b_chunk = (lane >> 3) & 1;

    // Precomputed ldsm base addresses (ks advances by +32 columns, XOR-free
    // part of the addr; the swizzle XOR depends only on row, so addr(ks) =
    // base ^ swz + ks*32 works because ks*32 toggles only bits >= 5 ... use
    // direct recompute, cheap).
    const int a_row = m_off + a_row_l;           // + mt*16
    const int b_row = n_off + b_row_l;           // + np*16

    // Hoisted staging geometry: 2048 16B-chunks per tile, 8 per thread.
    const __half* sp_base[8];
    uint32_t dst_off[8];
#pragma unroll
    for (int i = 0; i < 8; i++) {
        const int j = tid + i * 256;        // 0..2047
        const int plane = j >> 10;          // 0:A 1:B
        const int r = (j >> 3) & 127;
        const int c = j & 7;
        const __half* sp = (plane == 0) ? Ar : Wr;
        const int grow = (plane == 0 ? m0 : n0) + r;
        sp_base[i] = sp + (size_t)grow * CDIM + c * 8;
        dst_off[i] = (uint32_t)(plane * 16384 + r * 128 + ((c * 16) ^ ((r & 7) << 4)));
    }

    auto stage = [&](int t, uint32_t bufbase) {
        const int ke = t * 64;
#pragma unroll
        for (int i = 0; i < 8; i++)
            cp_async16(bufbase + dst_off[i], sp_base[i] + ke);
    };

    uint32_t buf0 = sbase, buf1 = sbase + STAGE_BYTES, buf2 = sbase + 2 * STAGE_BYTES;

    stage(0, buf0); CP_COMMIT();
    stage(1, buf1); CP_COMMIT();
    CP_WAIT(1);
    __syncthreads();

    uint32_t ah[2][2][4], bh[2][4][4];   // ping-pong fragments

    auto load_frags = [&](uint32_t cur, int ks, int pb) {
#pragma unroll
        for (int mt = 0; mt < 2; mt++) {
            const int row = a_row + mt * 16;
            const uint32_t addr = (uint32_t)(row * 128) +
                (((uint32_t)(ks * 32 + a_chunk * 16)) ^ (((uint32_t)(row & 7)) << 4));
            ldsm4(ah[pb][mt], cur + OFF_AH + addr);
        }
#pragma unroll
        for (int np = 0; np < 4; np++) {
            const int row = b_row + np * 16;
            const uint32_t addr = (uint32_t)(row * 128) +
                (((uint32_t)(ks * 32 + b_chunk * 16)) ^ (((uint32_t)(row & 7)) << 4));
            ldsm4(bh[pb][np], cur + OFF_BH + addr);
        }
    };

    for (int t = 0; t < NKT; t++) {
        const uint32_t cur = buf0;
        load_frags(cur, 0, 0);
#pragma unroll
        for (int ks = 0; ks < 4; ks++) {
            const int pb = ks & 1;
            if (ks < 3) load_frags(cur, ks + 1, pb ^ 1);
#pragma unroll
            for (int mt = 0; mt < 2; mt++)
#pragma unroll
                for (int np = 0; np < 4; np++) {
                    mma16816(acc[mt][np * 2],     ah[pb][mt], &bh[pb][np][0]);
                    mma16816(acc[mt][np * 2 + 1], ah[pb][mt], &bh[pb][np][2]);
                }
        }

        if (t + 1 >= NKT) break;
        if (t + 2 < NKT) {
            stage(t + 2, buf2); CP_COMMIT();
            CP_WAIT(1);
        } else {
            CP_WAIT(0);
        }
        __syncthreads();
        const uint32_t tmp = buf0; buf0 = buf1; buf1 = buf2; buf2 = tmp;
    }
}

// ===========================================================================
// Persistent merged QKV GEMM. Grid (PGRID): CTA loops over 1536 tiles.
// Q epilogue folds 0.125 * log2(e) for log2-domain softmax.
// ===========================================================================
__global__ __launch_bounds__(256, 2)
void gemm_qkv(const __half* __restrict__ Ar, QKVArgs args)
{
    extern __shared__ __align__(1024) char smem[];
    const uint32_t sbase = smem_u32(smem);

    const int lane = threadIdx.x & 31;
    const int wid  = threadIdx.x >> 5;
    const int m_off = (wid & 3) * 32;
    const int n_off = (wid >> 2) * 64;

    for (int tile = blockIdx.x; tile < QKV_TILES; tile += PGRID) {
        const int g    = tile % 3;
        const int n0   = ((tile / 3) % (CDIM / 128)) * 128;
        const int m0   = (tile / (3 * (CDIM / 128))) * 128;

        const __half* Wh  = (g == 0) ? args.W0 : (g == 1) ? args.W1 : args.W2;
        const float* bias = (g == 0) ? args.b0 : (g == 1) ? args.b1 : args.b2;
        __half* oh        = (g == 0) ? args.o0 : (g == 1) ? args.o1 : args.o2;
        const float scale = (g == 0) ? 0.125f * 1.44269504f : 1.0f;

        float acc[2][8][4];
#pragma unroll
        for (int mt = 0; mt < 2; mt++)
#pragma unroll
            for (int nt = 0; nt < 8; nt++)
#pragma unroll
                for (int e = 0; e < 4; e++) acc[mt][nt][e] = 0.0f;

        gemm_mainloop(Ar, Wh, m0, n0, sbase, acc);

#pragma unroll
        for (int mt = 0; mt < 2; mt++) {
#pragma unroll
            for (int nt = 0; nt < 8; nt++) {
                const int n  = n0 + n_off + nt * 8 + (lane & 3) * 2;
                const int r0 = m0 + m_off + mt * 16 + (lane >> 2);
                const int r1 = r0 + 8;
                const float b0 = bias[n], b1 = bias[n + 1];
                const int h = n >> 6, d = n & 63;
                const size_t o0 = (((size_t)((r0 >> 11) * HN + h) * TLEN) + (r0 & 2047)) * DD + d;
                const size_t o1 = (((size_t)((r1 >> 11) * HN + h) * TLEN) + (r1 & 2047)) * DD + d;
                *reinterpret_cast<uint32_t*>(oh + o0) =
                    round2((acc[mt][nt][0] + b0) * scale, (acc[mt][nt][1] + b1) * scale);
                *reinterpret_cast<uint32_t*>(oh + o1) =
                    round2((acc[mt][nt][2] + b0) * scale, (acc[mt][nt][3] + b1) * scale);
            }
        }
        __syncthreads();   // smem buffers reused by next tile
    }
}

// ===========================================================================
// Persistent projection GEMM (fp32 out, flat [M,N]).
// ===========================================================================
__global__ __launch_bounds__(256, 2)
void gemm_proj(const __half* __restrict__ Ar, const __half* __restrict__ Wr,
               const float* __restrict__ bias, float* __restrict__ out)
{
    extern __shared__ __align__(1024) char smem[];
    const uint32_t sbase = smem_u32(smem);

    const int lane = threadIdx.x & 31;
    const int wid  = threadIdx.x >> 5;
    const int m_off = (wid & 3) * 32;
    const int n_off = (wid >> 2) * 64;

    for (int tile = blockIdx.x; tile < PROJ_TILES; tile += PGRID) {
        const int n0 = (tile % (CDIM / 128)) * 128;
        const int m0 = (tile / (CDIM / 128)) * 128;

        float acc[2][8][4];
#pragma unroll
        for (int mt = 0; mt < 2; mt++)
#pragma unroll
            for (int nt = 0; nt < 8; nt++)
#pragma unroll
                for (int e = 0; e < 4; e++) acc[mt][nt][e] = 0.0f;

        gemm_mainloop(Ar, Wr, m0, n0, sbase, acc);

#pragma unroll
        for (int mt = 0; mt < 2; mt++) {
#pragma unroll
            for (int nt = 0; nt < 8; nt++) {
                const int n  = n0 + n_off + nt * 8 + (lane & 3) * 2;
                const int r0 = m0 + m_off + mt * 16 + (lane >> 2);
                const int r1 = r0 + 8;
                const float b0 = bias[n], b1 = bias[n + 1];
                *reinterpret_cast<float2*>(out + (size_t)r0 * CDIM + n) =
                    make_float2(acc[mt][nt][0] + b0, acc[mt][nt][1] + b1);
                *reinterpret_cast<float2*>(out + (size_t)r1 * CDIM + n) =
                    make_float2(acc[mt][nt][2] + b0, acc[mt][nt][3] + b1);
            }
        }
        __syncthreads();
    }
}

// ===========================================================================
// HMMA flash attention (causal), fp16 1-term, zero-shift log2 softmax
// (unchanged from R14): P = exp2(S) via ex2.approx.f16x2; l via ones-column
// MMA. CTA = 128 q x one (b,h), 256 threads, 4-stage KV ring, heavy first.
// ===========================================================================
#define AT_Q 0
#define AT_STAGE0 16384
#define AT_STAGE_BYTES 16384          // KH,VH each 8 KB
#define ATTN_SMEM (AT_STAGE0 + 4 * AT_STAGE_BYTES)   // 80 KB

__global__ __launch_bounds__(256, 2)
void flash_hmma(const __half* __restrict__ Qr,
                const __half* __restrict__ Kh, const __half* __restrict__ Vh,
                __half* __restrict__ Yr)
{
    extern __shared__ __align__(1024) char smem[];
    const uint32_t sbase = smem_u32(smem);

    const int tid  = threadIdx.x;
    const int lane = tid & 31;
    const int w    = tid >> 5;
    const int gid  = lane >> 2;
    const int tig  = lane & 3;
    const int bh = blockIdx.y;
    const int b  = bh >> 4;
    const int h  = bh & 15;
    const int bx = (int)gridDim.x - 1 - (int)blockIdx.x;   // heavy tiles first
    const int qbase = bx * 128;
    const int last = 2 * bx + 1;

    const size_t bh_off = (size_t)bh * TLEN * DD;

    const int a_row_l = ((lane >> 3) & 1) * 8 + (lane & 7);
    const int a_chunk = lane >> 4;
    const int b_row_l = ((lane >> 4) & 1) * 8 + (lane & 7);
    const int b_chunk = (lane >> 3) & 1;

    const uint32_t vone = (lane < 4) ? 0x3C003C00u : 0u;
    const uint32_t vfrag[2] = {vone, vone};

    const __half* kv_base[4];
    uint32_t kv_dst[4];
#pragma unroll
    for (int i = 0; i < 4; i++) {
        const int j = tid + i * 256;
        const int plane = j >> 9;           // 0:KH 1:VH
        const int r = (j >> 3) & 63;
        const int c = j & 7;
        const __half* sp = (plane == 0) ? Kh : Vh;
        kv_base[i] = sp + bh_off + (size_t)r * DD + c * 8;
        kv_dst[i]  = sbase + AT_STAGE0 +
                     (uint32_t)(plane * 8192 + r * 128 + ((c * 16) ^ ((r & 7) << 4)));
    }

    auto issue_KV = [&](int kt) {
        const int ke = kt * 64 * DD;
        const uint32_t boff = (uint32_t)((kt & 3) * AT_STAGE_BYTES);
#pragma unroll
        for (int i = 0; i < 4; i++)
            cp_async16(kv_dst[i] + boff, kv_base[i] + ke);
    };

    {
#pragma unroll
        for (int i = 0; i < 4; i++) {
            const int j = tid + i * 256;
            const int r = j >> 3;
            const int c = j & 7;
            const __half* src = Qr + bh_off + (size_t)(qbase + r) * DD + c * 8;
            const uint32_t dst = sbase + (uint32_t)(r * 128 + ((c * 16) ^ ((r & 7) << 4)));
            cp_async16(dst, src);
        }
    }
    issue_KV(0); CP_COMMIT();
    issue_KV(1); CP_COMMIT();
    if (2 <= last) { issue_KV(2); CP_COMMIT(); CP_WAIT(2); }
    else           { CP_WAIT(1); }
    __syncthreads();

    uint32_t qf[4][4];
#pragma unroll
    for (int ks = 0; ks < 4; ks++) {
        const int row = w * 16 + a_row_l;
        const uint32_t addr = (uint32_t)(row * 128) +
            (((uint32_t)(ks * 32 + a_chunk * 16)) ^ (((uint32_t)(row & 7)) << 4));
        ldsm4(qf[ks], sbase + AT_Q + addr);
    }

    float O[8][4];
#pragma unroll
    for (int nt = 0; nt < 8; nt++)
#pragma unroll
        for (int e = 0; e < 4; e++) O[nt][e] = 0.0f;
    float Ol[4] = {0.0f, 0.0f, 0.0f, 0.0f};

    const int q0 = qbase + w * 16 + gid;
    const int q1 = q0 + 8;

    for (int kt = 0; kt <= last; kt++) {
        const uint32_t stg = sbase + AT_STAGE0 + (uint32_t)((kt & 3) * AT_STAGE_BYTES);
        const uint32_t sKH = stg, sVH = stg + 8192;

        float S[8][4];
#pragma unroll
        for (int nt = 0; nt < 8; nt++)
#pragma unroll
            for (int e = 0; e < 4; e++) S[nt][e] = 0.0f;

#pragma unroll
        for (int ks = 0; ks < 4; ks++) {
            uint32_t kfh[4][4];
#pragma unroll
            for (int np = 0; np < 4; np++) {
                const int row = np * 16 + b_row_l;
                const uint32_t addr = (uint32_t)(row * 128) +
                    (((uint32_t)(ks * 32 + b_chunk * 16)) ^ (((uint32_t)(row & 7)) << 4));
                ldsm4(kfh[np], sKH + addr);
            }
#pragma unroll
            for (int np = 0; np < 4; np++) {
                mma16816(S[2 * np],     qf[ks], &kfh[np][0]);
                mma16816(S[2 * np + 1], qf[ks], &kfh[np][2]);
            }
        }

        if (kt >= 2 * bx) {
#pragma unroll
            for (int nt = 0; nt < 8; nt++) {
                const int k0 = kt * 64 + nt * 8 + 2 * tig;
                if (k0     > q0) S[nt][0] = -1e4f;
                if (k0 + 1 > q0) S[nt][1] = -1e4f;
                if (k0     > q1) S[nt][2] = -1e4f;
                if (k0 + 1 > q1) S[nt][3] = -1e4f;
            }
        }

        uint32_t pf[4][4];
#pragma unroll
        for (int ks = 0; ks < 4; ks++) {
            pf[ks][0] = ex2h2(round2(S[2 * ks][0],     S[2 * ks][1]));
            pf[ks][1] = ex2h2(round2(S[2 * ks][2],     S[2 * ks][3]));
            pf[ks][2] = ex2h2(round2(S[2 * ks + 1][0], S[2 * ks + 1][1]));
            pf[ks][3] = ex2h2(round2(S[2 * ks + 1][2], S[2 * ks + 1][3]));
        }

#pragma unroll
        for (int ks = 0; ks < 4; ks++) {
            uint32_t vfh[4][4];
#pragma unroll
            for (int db = 0; db < 4; db++) {
                const int row = ks * 16 + a_row_l;
                const uint32_t addr = (uint32_t)(row * 128) +
                    (((uint32_t)(db * 32 + a_chunk * 16)) ^ (((uint32_t)(row & 7)) << 4));
                ldsm4t(vfh[db], sVH + addr);
            }
#pragma unroll
            for (int db = 0; db < 4; db++) {
                mma16816(O[2 * db],     pf[ks], &vfh[db][0]);
                mma16816(O[2 * db + 1], pf[ks], &vfh[db][2]);
            }
            mma16816(Ol, pf[ks], vfrag);
        }

        if (kt == last) break;
        if (kt + 3 <= last) {
            issue_KV(kt + 3); CP_COMMIT();
            CP_WAIT(2);
        } else {
            CP_WAIT(0);
        }
        __syncthreads();
    }

    const float l0 = __shfl_sync(0xffffffffu, Ol[0], lane & ~3);
    const float l1 = __shfl_sync(0xffffffffu, Ol[2], lane & ~3);
    const float inv0 = 1.0f / l0;
    const float inv1 = 1.0f / l1;
    __half* y0 = Yr + ((size_t)b * TLEN + q0) * CDIM + h * 64;
    __half* y1 = Yr + ((size_t)b * TLEN + q1) * CDIM + h * 64;
#pragma unroll
    for (int nt = 0; nt < 8; nt++) {
        const int col = nt * 8 + 2 * tig;
        *reinterpret_cast<uint32_t*>(y0 + col) = round2(O[nt][0] * inv0, O[nt][1] * inv0);
        *reinterpret_cast<uint32_t*>(y1 + col) = round2(O[nt][2] * inv1, O[nt][3] * inv1);
    }
}

// ---------------------------------------------------------------------------
extern "C" void kernel_launch(void* const* d_in, const int* in_sizes, int n_in,
                              void* d_out, int out_size)
{
    const float* x  = (const float*)d_in[0];
    const float* Wq = (const float*)d_in[1];
    const float* bq = (const float*)d_in[2];
    const float* Wk = (const float*)d_in[3];
    const float* bk = (const float*)d_in[4];
    const float* Wv = (const float*)d_in[5];
    const float* bv = (const float*)d_in[6];
    const float* Wp = (const float*)d_in[7];
    const float* bp = (const float*)d_in[8];
    float* out = (float*)d_out;

    __half *xr, *wq, *wk, *wv, *wp;
    __half *qr, *kh, *vh, *yr;
    cudaGetSymbolAddress((void**)&xr, g_xr);
    cudaGetSymbolAddress((void**)&wq, g_wq); cudaGetSymbolAddress((void**)&wk, g_wk);
    cudaGetSymbolAddress((void**)&wv, g_wv); cudaGetSymbolAddress((void**)&wp, g_wp);
    cudaGetSymbolAddress((void**)&qr, g_qr);
    cudaGetSymbolAddress((void**)&kh, g_kh); cudaGetSymbolAddress((void**)&vh, g_vh);
    cudaGetSymbolAddress((void**)&yr, g_yr);

    cudaFuncSetAttribute(gemm_qkv,  cudaFuncAttributeMaxDynamicSharedMemorySize, GEMM_SMEM);
    cudaFuncSetAttribute(gemm_proj, cudaFuncAttributeMaxDynamicSharedMemorySize, GEMM_SMEM);
    cudaFuncSetAttribute(flash_hmma, cudaFuncAttributeMaxDynamicSharedMemorySize, ATTN_SMEM);

    round_fp32<<<MROWS * CDIM / 1024, 256>>>(x, xr);
    W4Args wargs;
    wargs.s0 = Wq; wargs.s1 = Wk; wargs.s2 = Wv; wargs.s3 = Wp;
    wargs.d0 = wq; wargs.d1 = wk; wargs.d2 = wv; wargs.d3 = wp;
    round_w4<<<dim3(CDIM * CDIM / 1024, 4), 256>>>(wargs);

    QKVArgs args;
    args.W0 = wq; args.W1 = wk; args.W2 = wv;
    args.b0 = bq; args.b1 = bk; args.b2 = bv;
    args.o0 = qr; args.o1 = kh; args.o2 = vh;

    gemm_qkv<<<PGRID, 256, GEMM_SMEM>>>(xr, args);

    dim3 attn_grid(TLEN / 128, BSZ * HN);         // (16, 64)
    flash_hmma<<<attn_grid, 256, ATTN_SMEM>>>(qr, kh, vh, yr);

    gemm_proj<<<PGRID, 256, GEMM_SMEM>>>(yr, wp, bp, out);
}

// round 16
// speedup vs baseline: 1.0319x; 1.0319x over previous
#include <cuda_runtime.h>
#include <cuda_fp16.h>
#include <cstdint>

// Problem constants
#define BSZ  4
#define TLEN 2048
#define CDIM 1024
#define HN   16
#define DD   64
#define MROWS (BSZ * TLEN)   // 8192

// ---------------------------------------------------------------------------
// fp16 planes (device-global scratch; allocation-free)
// ---------------------------------------------------------------------------
__device__ __half g_xr[MROWS * CDIM];                      // x rounded
__device__ __half g_wq[CDIM * CDIM], g_wk[CDIM * CDIM];
__device__ __half g_wv[CDIM * CDIM], g_wp[CDIM * CDIM];
__device__ __half g_qr[MROWS * CDIM];                      // Q rounded (log2e-scaled)
__device__ __half g_kh[MROWS * CDIM];                      // K rounded
__device__ __half g_vh[MROWS * CDIM];                      // V rounded
__device__ __half g_yr[MROWS * CDIM];                      // Y rounded [B,T,C]

// ===========================================================================
// Helpers
// ===========================================================================
__device__ __forceinline__ uint32_t smem_u32(const void* p) {
    uint32_t a;
    asm("{ .reg .u64 t; cvta.to.shared.u64 t, %1; cvt.u32.u64 %0, t; }"
        : "=r"(a) : "l"(p));
    return a;
}

__device__ __forceinline__ void ldsm4(uint32_t* r, uint32_t addr) {
    asm volatile("ldmatrix.sync.aligned.m8n8.x4.shared.b16 {%0,%1,%2,%3}, [%4];"
        : "=r"(r[0]), "=r"(r[1]), "=r"(r[2]), "=r"(r[3]) : "r"(addr));
}

__device__ __forceinline__ void ldsm4t(uint32_t* r, uint32_t addr) {
    asm volatile("ldmatrix.sync.aligned.m8n8.x4.trans.shared.b16 {%0,%1,%2,%3}, [%4];"
        : "=r"(r[0]), "=r"(r[1]), "=r"(r[2]), "=r"(r[3]) : "r"(addr));
}

__device__ __forceinline__ void mma16816(float* c, const uint32_t* a,
                                         const uint32_t* b) {
    asm volatile(
        "mma.sync.aligned.m16n8k16.row.col.f32.f16.f16.f32 "
        "{%0,%1,%2,%3}, {%4,%5,%6,%7}, {%8,%9}, {%0,%1,%2,%3};"
        : "+f"(c[0]), "+f"(c[1]), "+f"(c[2]), "+f"(c[3])
        : "r"(a[0]), "r"(a[1]), "r"(a[2]), "r"(a[3]), "r"(b[0]), "r"(b[1]));
}

__device__ __forceinline__ uint32_t round2(float a, float b) {
    __half2 h = __floats2half2_rn(a, b);
    return *reinterpret_cast<uint32_t*>(&h);
}

// exp2 on a packed half2 (MUFU, 2 values per op)
__device__ __forceinline__ uint32_t ex2h2(uint32_t x) {
    uint32_t y;
    asm("ex2.approx.f16x2 %0, %1;" : "=r"(y) : "r"(x));
    return y;
}

__device__ __forceinline__ void cp_async16(uint32_t dst, const void* src) {
    asm volatile("cp.async.cg.shared.global [%0], [%1], 16;" :: "r"(dst), "l"(src));
}
#define CP_COMMIT() asm volatile("cp.async.commit_group;" ::: "memory")
#define CP_WAIT(n)  asm volatile("cp.async.wait_group %0;" :: "n"(n) : "memory")

// ===========================================================================
// Prep: round fp32 -> fp16.
// ===========================================================================
__global__ __launch_bounds__(256)
void round_fp32(const float* __restrict__ src, __half* __restrict__ dst)
{
    const int i = (blockIdx.x * 256 + threadIdx.x) * 4;
    const float4 v = *reinterpret_cast<const float4*>(src + i);
    *reinterpret_cast<uint2*>(dst + i) =
        make_uint2(round2(v.x, v.y), round2(v.z, v.w));
}

struct W4Args { const float* s0; const float* s1; const float* s2; const float* s3;
                __half* d0; __half* d1; __half* d2; __half* d3; };

__global__ __launch_bounds__(256)
void round_w4(W4Args a)
{
    const int g = blockIdx.y;
    const float* s = (g == 0) ? a.s0 : (g == 1) ? a.s1 : (g == 2) ? a.s2 : a.s3;
    __half* d      = (g == 0) ? a.d0 : (g == 1) ? a.d1 : (g == 2) ? a.d2 : a.d3;
    const int i = (blockIdx.x * 256 + threadIdx.x) * 4;
    const float4 v = *reinterpret_cast<const float4*>(s + i);
    *reinterpret_cast<uint2*>(d + i) =
        make_uint2(round2(v.x, v.y), round2(v.z, v.w));
}

// ===========================================================================
// GEMM skeleton: out = (A @ W^T + bias) * scale, fp16 1-term.
// CTA 128x128, K-tile 64, 3-stage cp.async ring, 256 threads,
// 8 warps (4M x 2N), warp tile 32x64. 2 CTAs/SM. Persistent CTAs.
// Sequential ks fragment loads (R14 form — fits 128-reg cap, no spills).
// ===========================================================================
#define NKT 16                        // 1024 / 64
#define STAGE_BYTES 32768             // A,B each 128*128B = 16 KB
#define OFF_AH 0
#define OFF_BH 16384
#define GEMM_SMEM (3 * STAGE_BYTES)   // 96 KB
#define PGRID 296                     // 148 SMs x 2 CTAs
#define QKV_TILES (3 * (CDIM / 128) * (MROWS / 128))   // 1536
#define PROJ_TILES ((CDIM / 128) * (MROWS / 128))      // 512

struct QKVArgs {
    const __half *W0, *W1, *W2;
    const float *b0, *b1, *b2;
    __half *o0, *o1, *o2;             // rounded single plane each
};

__device__ __forceinline__ void gemm_mainloop(
    const __half* __restrict__ Ar, const __half* __restrict__ Wr,
    int m0, int n0, uint32_t sbase, float acc[2][8][4])
{
    const int tid  = threadIdx.x;
    const int lane = tid & 31;
    const int wid  = tid >> 5;
    const int m_off = (wid & 3) * 32;
    const int n_off = (wid >> 2) * 64;

    const int a_row_l = ((lane >> 3) & 1) * 8 + (lane & 7);
    const int a_chunk = lane >> 4;
    const int b_row_l = ((lane >> 4) & 1) * 8 + (lane & 7);
    const int b_chunk = (lane >> 3) & 1;

    // Hoisted staging geometry: 2048 16B-chunks per tile, 8 per thread.
    const __half* sp_base[8];
    uint32_t dst_off[8];
#pragma unroll
    for (int i = 0; i < 8; i++) {
        const int j = tid + i * 256;        // 0..2047
        const int plane = j >> 10;          // 0:A 1:B
        const int r = (j >> 3) & 127;
        const int c = j & 7;
        const __half* sp = (plane == 0) ? Ar : Wr;
        const int grow = (plane == 0 ? m0 : n0) + r;
        sp_base[i] = sp + (size_t)grow * CDIM + c * 8;
        dst_off[i] = (uint32_t)(plane * 16384 + r * 128 + ((c * 16) ^ ((r & 7) << 4)));
    }

    auto stage = [&](int t, uint32_t bufbase) {
        const int ke = t * 64;
#pragma unroll
        for (int i = 0; i < 8; i++)
            cp_async16(bufbase + dst_off[i], sp_base[i] + ke);
    };

    uint32_t buf0 = sbase, buf1 = sbase + STAGE_BYTES, buf2 = sbase + 2 * STAGE_BYTES;

    stage(0, buf0); CP_COMMIT();
    stage(1, buf1); CP_COMMIT();
    CP_WAIT(1);
    __syncthreads();

    for (int t = 0; t < NKT; t++) {
        const uint32_t cur = buf0;
#pragma unroll
        for (int ks = 0; ks < 4; ks++) {
            uint32_t ah[2][4];
#pragma unroll
            for (int mt = 0; mt < 2; mt++) {
                const int row = m_off + mt * 16 + a_row_l;
                const uint32_t addr = (uint32_t)(row * 128) +
                    (((uint32_t)(ks * 32 + a_chunk * 16)) ^ (((uint32_t)(row & 7)) << 4));
                ldsm4(ah[mt], cur + OFF_AH + addr);
            }
            uint32_t bh[4][4];
#pragma unroll
            for (int np = 0; np < 4; np++) {
                const int row = n_off + np * 16 + b_row_l;
                const uint32_t addr = (uint32_t)(row * 128) +
                    (((uint32_t)(ks * 32 + b_chunk * 16)) ^ (((uint32_t)(row & 7)) << 4));
                ldsm4(bh[np], cur + OFF_BH + addr);
            }
#pragma unroll
            for (int mt = 0; mt < 2; mt++)
#pragma unroll
                for (int np = 0; np < 4; np++) {
                    mma16816(acc[mt][np * 2],     ah[mt], &bh[np][0]);
                    mma16816(acc[mt][np * 2 + 1], ah[mt], &bh[np][2]);
                }
        }

        if (t + 1 >= NKT) break;
        if (t + 2 < NKT) {
            stage(t + 2, buf2); CP_COMMIT();
            CP_WAIT(1);
        } else {
            CP_WAIT(0);
        }
        __syncthreads();
        const uint32_t tmp = buf0; buf0 = buf1; buf1 = buf2; buf2 = tmp;
    }
}

// ===========================================================================
// Persistent merged QKV GEMM. Grid (PGRID): CTA loops over 1536 tiles.
// Q epilogue folds 0.125 * log2(e) for log2-domain softmax.
// ===========================================================================
__global__ __launch_bounds__(256, 2)
void gemm_qkv(const __half* __restrict__ Ar, QKVArgs args)
{
    extern __shared__ __align__(1024) char smem[];
    const uint32_t sbase = smem_u32(smem);

    const int lane = threadIdx.x & 31;
    const int wid  = threadIdx.x >> 5;
    const int m_off = (wid & 3) * 32;
    const int n_off = (wid >> 2) * 64;

    for (int tile = blockIdx.x; tile < QKV_TILES; tile += PGRID) {
        const int g    = tile % 3;
        const int n0   = ((tile / 3) % (CDIM / 128)) * 128;
        const int m0   = (tile / (3 * (CDIM / 128))) * 128;

        const __half* Wh  = (g == 0) ? args.W0 : (g == 1) ? args.W1 : args.W2;
        const float* bias = (g == 0) ? args.b0 : (g == 1) ? args.b1 : args.b2;
        __half* oh        = (g == 0) ? args.o0 : (g == 1) ? args.o1 : args.o2;
        const float scale = (g == 0) ? 0.125f * 1.44269504f : 1.0f;

        float acc[2][8][4];
#pragma unroll
        for (int mt = 0; mt < 2; mt++)
#pragma unroll
            for (int nt = 0; nt < 8; nt++)
#pragma unroll
                for (int e = 0; e < 4; e++) acc[mt][nt][e] = 0.0f;

        gemm_mainloop(Ar, Wh, m0, n0, sbase, acc);

#pragma unroll
        for (int mt = 0; mt < 2; mt++) {
#pragma unroll
            for (int nt = 0; nt < 8; nt++) {
                const int n  = n0 + n_off + nt * 8 + (lane & 3) * 2;
                const int r0 = m0 + m_off + mt * 16 + (lane >> 2);
                const int r1 = r0 + 8;
                const float b0 = bias[n], b1 = bias[n + 1];
                const int h = n >> 6, d = n & 63;
                const size_t o0 = (((size_t)((r0 >> 11) * HN + h) * TLEN) + (r0 & 2047)) * DD + d;
                const size_t o1 = (((size_t)((r1 >> 11) * HN + h) * TLEN) + (r1 & 2047)) * DD + d;
                *reinterpret_cast<uint32_t*>(oh + o0) =
                    round2((acc[mt][nt][0] + b0) * scale, (acc[mt][nt][1] + b1) * scale);
                *reinterpret_cast<uint32_t*>(oh + o1) =
                    round2((acc[mt][nt][2] + b0) * scale, (acc[mt][nt][3] + b1) * scale);
            }
        }
        __syncthreads();   // smem buffers reused by next tile
    }
}

// ===========================================================================
// Persistent projection GEMM (fp32 out, flat [M,N]).
// ===========================================================================
__global__ __launch_bounds__(256, 2)
void gemm_proj(const __half* __restrict__ Ar, const __half* __restrict__ Wr,
               const float* __restrict__ bias, float* __restrict__ out)
{
    extern __shared__ __align__(1024) char smem[];
    const uint32_t sbase = smem_u32(smem);

    const int lane = threadIdx.x & 31;
    const int wid  = threadIdx.x >> 5;
    const int m_off = (wid & 3) * 32;
    const int n_off = (wid >> 2) * 64;

    for (int tile = blockIdx.x; tile < PROJ_TILES; tile += PGRID) {
        const int n0 = (tile % (CDIM / 128)) * 128;
        const int m0 = (tile / (CDIM / 128)) * 128;

        float acc[2][8][4];
#pragma unroll
        for (int mt = 0; mt < 2; mt++)
#pragma unroll
            for (int nt = 0; nt < 8; nt++)
#pragma unroll
                for (int e = 0; e < 4; e++) acc[mt][nt][e] = 0.0f;

        gemm_mainloop(Ar, Wr, m0, n0, sbase, acc);

#pragma unroll
        for (int mt = 0; mt < 2; mt++) {
#pragma unroll
            for (int nt = 0; nt < 8; nt++) {
                const int n  = n0 + n_off + nt * 8 + (lane & 3) * 2;
                const int r0 = m0 + m_off + mt * 16 + (lane >> 2);
                const int r1 = r0 + 8;
                const float b0 = bias[n], b1 = bias[n + 1];
                *reinterpret_cast<float2*>(out + (size_t)r0 * CDIM + n) =
                    make_float2(acc[mt][nt][0] + b0, acc[mt][nt][1] + b1);
                *reinterpret_cast<float2*>(out + (size_t)r1 * CDIM + n) =
                    make_float2(acc[mt][nt][2] + b0, acc[mt][nt][3] + b1);
            }
        }
        __syncthreads();
    }
}

// ===========================================================================
// HMMA flash attention (causal), fp16 1-term, zero-shift log2 softmax
// (unchanged from R14): P = exp2(S) via ex2.approx.f16x2; l via ones-column
// MMA. CTA = 128 q x one (b,h), 256 threads, 4-stage KV ring, heavy first.
// ===========================================================================
#define AT_Q 0
#define AT_STAGE0 16384
#define AT_STAGE_BYTES 16384          // KH,VH each 8 KB
#define ATTN_SMEM (AT_STAGE0 + 4 * AT_STAGE_BYTES)   // 80 KB

__global__ __launch_bounds__(256, 2)
void flash_hmma(const __half* __restrict__ Qr,
                const __half* __restrict__ Kh, const __half* __restrict__ Vh,
                __half* __restrict__ Yr)
{
    extern __shared__ __align__(1024) char smem[];
    const uint32_t sbase = smem_u32(smem);

    const int tid  = threadIdx.x;
    const int lane = tid & 31;
    const int w    = tid >> 5;
    const int gid  = lane >> 2;
    const int tig  = lane & 3;
    const int bh = blockIdx.y;
    const int b  = bh >> 4;
    const int h  = bh & 15;
    const int bx = (int)gridDim.x - 1 - (int)blockIdx.x;   // heavy tiles first
    const int qbase = bx * 128;
    const int last = 2 * bx + 1;

    const size_t bh_off = (size_t)bh * TLEN * DD;

    const int a_row_l = ((lane >> 3) & 1) * 8 + (lane & 7);
    const int a_chunk = lane >> 4;
    const int b_row_l = ((lane >> 4) & 1) * 8 + (lane & 7);
    const int b_chunk = (lane >> 3) & 1;

    const uint32_t vone = (lane < 4) ? 0x3C003C00u : 0u;
    const uint32_t vfrag[2] = {vone, vone};

    const __half* kv_base[4];
    uint32_t kv_dst[4];
#pragma unroll
    for (int i = 0; i < 4; i++) {
        const int j = tid + i * 256;
        const int plane = j >> 9;           // 0:KH 1:VH
        const int r = (j >> 3) & 63;
        const int c = j & 7;
        const __half* sp = (plane == 0) ? Kh : Vh;
        kv_base[i] = sp + bh_off + (size_t)r * DD + c * 8;
        kv_dst[i]  = sbase + AT_STAGE0 +
                     (uint32_t)(plane * 8192 + r * 128 + ((c * 16) ^ ((r & 7) << 4)));
    }

    auto issue_KV = [&](int kt) {
        const int ke = kt * 64 * DD;
        const uint32_t boff = (uint32_t)((kt & 3) * AT_STAGE_BYTES);
#pragma unroll
        for (int i = 0; i < 4; i++)
            cp_async16(kv_dst[i] + boff, kv_base[i] + ke);
    };

    {
#pragma unroll
        for (int i = 0; i < 4; i++) {
            const int j = tid + i * 256;
            const int r = j >> 3;
            const int c = j & 7;
            const __half* src = Qr + bh_off + (size_t)(qbase + r) * DD + c * 8;
            const uint32_t dst = sbase + (uint32_t)(r * 128 + ((c * 16) ^ ((r & 7) << 4)));
            cp_async16(dst, src);
        }
    }
    issue_KV(0); CP_COMMIT();
    issue_KV(1); CP_COMMIT();
    if (2 <= last) { issue_KV(2); CP_COMMIT(); CP_WAIT(2); }
    else           { CP_WAIT(1); }
    __syncthreads();

    uint32_t qf[4][4];
#pragma unroll
    for (int ks = 0; ks < 4; ks++) {
        const int row = w * 16 + a_row_l;
        const uint32_t addr = (uint32_t)(row * 128) +
            (((uint32_t)(ks * 32 + a_chunk * 16)) ^ (((uint32_t)(row & 7)) << 4));
        ldsm4(qf[ks], sbase + AT_Q + addr);
    }

    float O[8][4];
#pragma unroll
    for (int nt = 0; nt < 8; nt++)
#pragma unroll
        for (int e = 0; e < 4; e++) O[nt][e] = 0.0f;
    float Ol[4] = {0.0f, 0.0f, 0.0f, 0.0f};

    const int q0 = qbase + w * 16 + gid;
    const int q1 = q0 + 8;

    for (int kt = 0; kt <= last; kt++) {
        const uint32_t stg = sbase + AT_STAGE0 + (uint32_t)((kt & 3) * AT_STAGE_BYTES);
        const uint32_t sKH = stg, sVH = stg + 8192;

        float S[8][4];
#pragma unroll
        for (int nt = 0; nt < 8; nt++)
#pragma unroll
            for (int e = 0; e < 4; e++) S[nt][e] = 0.0f;

#pragma unroll
        for (int ks = 0; ks < 4; ks++) {
            uint32_t kfh[4][4];
#pragma unroll
            for (int np = 0; np < 4; np++) {
                const int row = np * 16 + b_row_l;
                const uint32_t addr = (uint32_t)(row * 128) +
                    (((uint32_t)(ks * 32 + b_chunk * 16)) ^ (((uint32_t)(row & 7)) << 4));
                ldsm4(kfh[np], sKH + addr);
            }
#pragma unroll
            for (int np = 0; np < 4; np++) {
                mma16816(S[2 * np],     qf[ks], &kfh[np][0]);
                mma16816(S[2 * np + 1], qf[ks], &kfh[np][2]);
            }
        }

        if (kt >= 2 * bx) {
#pragma unroll
            for (int nt = 0; nt < 8; nt++) {
                const int k0 = kt * 64 + nt * 8 + 2 * tig;
                if (k0     > q0) S[nt][0] = -1e4f;
                if (k0 + 1 > q0) S[nt][1] = -1e4f;
                if (k0     > q1) S[nt][2] = -1e4f;
                if (k0 + 1 > q1) S[nt][3] = -1e4f;
            }
        }

        uint32_t pf[4][4];
#pragma unroll
        for (int ks = 0; ks < 4; ks++) {
            pf[ks][0] = ex2h2(round2(S[2 * ks][0],     S[2 * ks][1]));
            pf[ks][1] = ex2h2(round2(S[2 * ks][2],     S[2 * ks][3]));
            pf[ks][2] = ex2h2(round2(S[2 * ks + 1][0], S[2 * ks + 1][1]));
            pf[ks][3] = ex2h2(round2(S[2 * ks + 1][2], S[2 * ks + 1][3]));
        }

#pragma unroll
        for (int ks = 0; ks < 4; ks++) {
            uint32_t vfh[4][4];
#pragma unroll
            for (int db = 0; db < 4; db++) {
                const int row = ks * 16 + a_row_l;
                const uint32_t addr = (uint32_t)(row * 128) +
                    (((uint32_t)(db * 32 + a_chunk * 16)) ^ (((uint32_t)(row & 7)) << 4));
                ldsm4t(vfh[db], sVH + addr);
            }
#pragma unroll
            for (int db = 0; db < 4; db++) {
                mma16816(O[2 * db],     pf[ks], &vfh[db][0]);
                mma16816(O[2 * db + 1], pf[ks], &vfh[db][2]);
            }
            mma16816(Ol, pf[ks], vfrag);
        }

        if (kt == last) break;
        if (kt + 3 <= last) {
            issue_KV(kt + 3); CP_COMMIT();
            CP_WAIT(2);
        } else {
            CP_WAIT(0);
        }
        __syncthreads();
    }

    const float l0 = __shfl_sync(0xffffffffu, Ol[0], lane & ~3);
    const float l1 = __shfl_sync(0xffffffffu, Ol[2], lane & ~3);
    const float inv0 = 1.0f / l0;
    const float inv1 = 1.0f / l1;
    __half* y0 = Yr + ((size_t)b * TLEN + q0) * CDIM + h * 64;
    __half* y1 = Yr + ((size_t)b * TLEN + q1) * CDIM + h * 64;
#pragma unroll
    for (int nt = 0; nt < 8; nt++) {
        const int col = nt * 8 + 2 * tig;
        *reinterpret_cast<uint32_t*>(y0 + col) = round2(O[nt][0] * inv0, O[nt][1] * inv0);
        *reinterpret_cast<uint32_t*>(y1 + col) = round2(O[nt][2] * inv1, O[nt][3] * inv1);
    }
}

// ---------------------------------------------------------------------------
extern "C" void kernel_launch(void* const* d_in, const int* in_sizes, int n_in,
                              void* d_out, int out_size)
{
    const float* x  = (const float*)d_in[0];
    const float* Wq = (const float*)d_in[1];
    const float* bq = (const float*)d_in[2];
    const float* Wk = (const float*)d_in[3];
    const float* bk = (const float*)d_in[4];
    const float* Wv = (const float*)d_in[5];
    const float* bv = (const float*)d_in[6];
    const float* Wp = (const float*)d_in[7];
    const float* bp = (const float*)d_in[8];
    float* out = (float*)d_out;

    __half *xr, *wq, *wk, *wv, *wp;
    __half *qr, *kh, *vh, *yr;
    cudaGetSymbolAddress((void**)&xr, g_xr);
    cudaGetSymbolAddress((void**)&wq, g_wq); cudaGetSymbolAddress((void**)&wk, g_wk);
    cudaGetSymbolAddress((void**)&wv, g_wv); cudaGetSymbolAddress((void**)&wp, g_wp);
    cudaGetSymbolAddress((void**)&qr, g_qr);
    cudaGetSymbolAddress((void**)&kh, g_kh); cudaGetSymbolAddress((void**)&vh, g_vh);
    cudaGetSymbolAddress((void**)&yr, g_yr);

    cudaFuncSetAttribute(gemm_qkv,  cudaFuncAttributeMaxDynamicSharedMemorySize, GEMM_SMEM);
    cudaFuncSetAttribute(gemm_proj, cudaFuncAttributeMaxDynamicSharedMemorySize, GEMM_SMEM);
    cudaFuncSetAttribute(flash_hmma, cudaFuncAttributeMaxDynamicSharedMemorySize, ATTN_SMEM);

    round_fp32<<<MROWS * CDIM / 1024, 256>>>(x, xr);
    W4Args wargs;
    wargs.s0 = Wq; wargs.s1 = Wk; wargs.s2 = Wv; wargs.s3 = Wp;
    wargs.d0 = wq; wargs.d1 = wk; wargs.d2 = wv; wargs.d3 = wp;
    round_w4<<<dim3(CDIM * CDIM / 1024, 4), 256>>>(wargs);

    QKVArgs args;
    args.W0 = wq; args.W1 = wk; args.W2 = wv;
    args.b0 = bq; args.b1 = bk; args.b2 = bv;
    args.o0 = qr; args.o1 = kh; args.o2 = vh;

    gemm_qkv<<<PGRID, 256, GEMM_SMEM>>>(xr, args);

    dim3 attn_grid(TLEN / 128, BSZ * HN);         // (16, 64)
    flash_hmma<<<attn_grid, 256, ATTN_SMEM>>>(qr, kh, vh, yr);

    gemm_proj<<<PGRID, 256, GEMM_SMEM>>>(yr, wp, bp, out);
}

// round 17
// speedup vs baseline: 1.0751x; 1.0419x over previous
#include <cuda_runtime.h>
#include <cuda_fp16.h>
#include <cstdint>

// Problem constants
#define BSZ  4
#define TLEN 2048
#define CDIM 1024
#define HN   16
#define DD   64
#define MROWS (BSZ * TLEN)   // 8192

// ---------------------------------------------------------------------------
// fp16 planes (device-global scratch; allocation-free)
// ---------------------------------------------------------------------------
__device__ __half g_xr[MROWS * CDIM];                      // x rounded
__device__ __half g_wq[CDIM * CDIM], g_wk[CDIM * CDIM];
__device__ __half g_wv[CDIM * CDIM], g_wp[CDIM * CDIM];
__device__ __half g_qr[MROWS * CDIM];                      // Q rounded (log2e-scaled)
__device__ __half g_kh[MROWS * CDIM];                      // K rounded
__device__ __half g_vh[MROWS * CDIM];                      // V rounded
__device__ __half g_yr[MROWS * CDIM];                      // Y rounded [B,T,C]

// ===========================================================================
// Helpers
// ===========================================================================
__device__ __forceinline__ uint32_t smem_u32(const void* p) {
    uint32_t a;
    asm("{ .reg .u64 t; cvta.to.shared.u64 t, %1; cvt.u32.u64 %0, t; }"
        : "=r"(a) : "l"(p));
    return a;
}

__device__ __forceinline__ void ldsm4(uint32_t* r, uint32_t addr) {
    asm volatile("ldmatrix.sync.aligned.m8n8.x4.shared.b16 {%0,%1,%2,%3}, [%4];"
        : "=r"(r[0]), "=r"(r[1]), "=r"(r[2]), "=r"(r[3]) : "r"(addr));
}

__device__ __forceinline__ void ldsm4t(uint32_t* r, uint32_t addr) {
    asm volatile("ldmatrix.sync.aligned.m8n8.x4.trans.shared.b16 {%0,%1,%2,%3}, [%4];"
        : "=r"(r[0]), "=r"(r[1]), "=r"(r[2]), "=r"(r[3]) : "r"(addr));
}

__device__ __forceinline__ void mma16816(float* c, const uint32_t* a,
                                         const uint32_t* b) {
    asm volatile(
        "mma.sync.aligned.m16n8k16.row.col.f32.f16.f16.f32 "
        "{%0,%1,%2,%3}, {%4,%5,%6,%7}, {%8,%9}, {%0,%1,%2,%3};"
        : "+f"(c[0]), "+f"(c[1]), "+f"(c[2]), "+f"(c[3])
        : "r"(a[0]), "r"(a[1]), "r"(a[2]), "r"(a[3]), "r"(b[0]), "r"(b[1]));
}

__device__ __forceinline__ uint32_t round2(float a, float b) {
    __half2 h = __floats2half2_rn(a, b);
    return *reinterpret_cast<uint32_t*>(&h);
}

// exp2 on a packed half2 (MUFU, 2 values per op)
__device__ __forceinline__ uint32_t ex2h2(uint32_t x) {
    uint32_t y;
    asm("ex2.approx.f16x2 %0, %1;" : "=r"(y) : "r"(x));
    return y;
}

__device__ __forceinline__ void cp_async16(uint32_t dst, const void* src) {
    asm volatile("cp.async.cg.shared.global [%0], [%1], 16;" :: "r"(dst), "l"(src));
}
#define CP_COMMIT() asm volatile("cp.async.commit_group;" ::: "memory")
#define CP_WAIT(n)  asm volatile("cp.async.wait_group %0;" :: "n"(n) : "memory")

// ===========================================================================
// Fused prep: round x and all four W matrices fp32 -> fp16 in ONE launch.
// Flattened 1D grid: blocks [0, 8192) -> x; then 1024 blocks per W.
// ===========================================================================
struct PrepArgs {
    const float *x, *wq, *wk, *wv, *wp;
    __half *xr, *dq, *dk, *dv, *dp;
};

__global__ __launch_bounds__(256)
void round_all(PrepArgs a)
{
    const int blk = blockIdx.x;
    const float* s;
    __half* d;
    int base;
    if (blk < 8192)      { s = a.x;  d = a.xr; base = blk; }
    else if (blk < 9216) { s = a.wq; d = a.dq; base = blk - 8192; }
    else if (blk < 10240){ s = a.wk; d = a.dk; base = blk - 9216; }
    else if (blk < 11264){ s = a.wv; d = a.dv; base = blk - 10240; }
    else                 { s = a.wp; d = a.dp; base = blk - 11264; }
    const int i = (base * 256 + threadIdx.x) * 4;
    const float4 v = *reinterpret_cast<const float4*>(s + i);
    *reinterpret_cast<uint2*>(d + i) =
        make_uint2(round2(v.x, v.y), round2(v.z, v.w));
}

// ===========================================================================
// GEMM skeleton: out = (A @ W^T + bias) * scale, fp16 1-term.
// CTA 128x128, K-tile 64, 3-stage cp.async ring, 256 threads,
// 8 warps (4M x 2N), warp tile 32x64. 2 CTAs/SM. (R14 configuration.)
// ===========================================================================
#define NKT 16                        // 1024 / 64
#define STAGE_BYTES 32768             // A,B each 128*128B = 16 KB
#define OFF_AH 0
#define OFF_BH 16384
#define GEMM_SMEM (3 * STAGE_BYTES)   // 96 KB

struct QKVArgs {
    const __half *W0, *W1, *W2;
    const float *b0, *b1, *b2;
    __half *o0, *o1, *o2;             // rounded single plane each
};

__device__ __forceinline__ void gemm_mainloop(
    const __half* __restrict__ Ar, const __half* __restrict__ Wr,
    int m0, int n0, uint32_t sbase, float acc[2][8][4])
{
    const int tid  = threadIdx.x;
    const int lane = tid & 31;
    const int wid  = tid >> 5;
    const int m_off = (wid & 3) * 32;
    const int n_off = (wid >> 2) * 64;

    const int a_row_l = ((lane >> 3) & 1) * 8 + (lane & 7);
    const int a_chunk = lane >> 4;
    const int b_row_l = ((lane >> 4) & 1) * 8 + (lane & 7);
    const int b_chunk = (lane >> 3) & 1;

    // Hoisted staging geometry: 2048 16B-chunks per tile, 8 per thread.
    const __half* sp_base[8];
    uint32_t dst_off[8];
#pragma unroll
    for (int i = 0; i < 8; i++) {
        const int j = tid + i * 256;        // 0..2047
        const int plane = j >> 10;          // 0:A 1:B
        const int r = (j >> 3) & 127;
        const int c = j & 7;
        const __half* sp = (plane == 0) ? Ar : Wr;
        const int grow = (plane == 0 ? m0 : n0) + r;
        sp_base[i] = sp + (size_t)grow * CDIM + c * 8;
        dst_off[i] = (uint32_t)(plane * 16384 + r * 128 + ((c * 16) ^ ((r & 7) << 4)));
    }

    auto stage = [&](int t, uint32_t bufbase) {
        const int ke = t * 64;
#pragma unroll
        for (int i = 0; i < 8; i++)
            cp_async16(bufbase + dst_off[i], sp_base[i] + ke);
    };

    uint32_t buf0 = sbase, buf1 = sbase + STAGE_BYTES, buf2 = sbase + 2 * STAGE_BYTES;

    stage(0, buf0); CP_COMMIT();
    stage(1, buf1); CP_COMMIT();
    CP_WAIT(1);
    __syncthreads();

    for (int t = 0; t < NKT; t++) {
        const uint32_t cur = buf0;
#pragma unroll
        for (int ks = 0; ks < 4; ks++) {
            uint32_t ah[2][4];
#pragma unroll
            for (int mt = 0; mt < 2; mt++) {
                const int row = m_off + mt * 16 + a_row_l;
                const uint32_t addr = (uint32_t)(row * 128) +
                    (((uint32_t)(ks * 32 + a_chunk * 16)) ^ (((uint32_t)(row & 7)) << 4));
                ldsm4(ah[mt], cur + OFF_AH + addr);
            }
            uint32_t bh[4][4];
#pragma unroll
            for (int np = 0; np < 4; np++) {
                const int row = n_off + np * 16 + b_row_l;
                const uint32_t addr = (uint32_t)(row * 128) +
                    (((uint32_t)(ks * 32 + b_chunk * 16)) ^ (((uint32_t)(row & 7)) << 4));
                ldsm4(bh[np], cur + OFF_BH + addr);
            }
#pragma unroll
            for (int mt = 0; mt < 2; mt++)
#pragma unroll
                for (int np = 0; np < 4; np++) {
                    mma16816(acc[mt][np * 2],     ah[mt], &bh[np][0]);
                    mma16816(acc[mt][np * 2 + 1], ah[mt], &bh[np][2]);
                }
        }

        if (t + 1 >= NKT) break;
        if (t + 2 < NKT) {
            stage(t + 2, buf2); CP_COMMIT();
            CP_WAIT(1);
        } else {
            CP_WAIT(0);
        }
        __syncthreads();
        const uint32_t tmp = buf0; buf0 = buf1; buf1 = buf2; buf2 = tmp;
    }
}

// ===========================================================================
// Merged QKV GEMM. Grid (24, 64): blockIdx.x = nblk*3 + gemm_id.
// Q epilogue folds 0.125 * log2(e) for log2-domain softmax.
// ===========================================================================
__global__ __launch_bounds__(256, 2)
void gemm_qkv(const __half* __restrict__ Ar, QKVArgs args)
{
    extern __shared__ __align__(1024) char smem[];
    const uint32_t sbase = smem_u32(smem);

    const int g    = blockIdx.x % 3;
    const int n0   = (blockIdx.x / 3) * 128;
    const int m0   = blockIdx.y * 128;

    const __half* Wh  = (g == 0) ? args.W0 : (g == 1) ? args.W1 : args.W2;
    const float* bias = (g == 0) ? args.b0 : (g == 1) ? args.b1 : args.b2;
    __half* oh        = (g == 0) ? args.o0 : (g == 1) ? args.o1 : args.o2;
    const float scale = (g == 0) ? 0.125f * 1.44269504f : 1.0f;

    float acc[2][8][4];
#pragma unroll
    for (int mt = 0; mt < 2; mt++)
#pragma unroll
        for (int nt = 0; nt < 8; nt++)
#pragma unroll
            for (int e = 0; e < 4; e++) acc[mt][nt][e] = 0.0f;

    gemm_mainloop(Ar, Wh, m0, n0, sbase, acc);

    const int lane = threadIdx.x & 31;
    const int wid  = threadIdx.x >> 5;
    const int m_off = (wid & 3) * 32;
    const int n_off = (wid >> 2) * 64;

#pragma unroll
    for (int mt = 0; mt < 2; mt++) {
#pragma unroll
        for (int nt = 0; nt < 8; nt++) {
            const int n  = n0 + n_off + nt * 8 + (lane & 3) * 2;
            const int r0 = m0 + m_off + mt * 16 + (lane >> 2);
            const int r1 = r0 + 8;
            const float b0 = bias[n], b1 = bias[n + 1];
            const int h = n >> 6, d = n & 63;
            const size_t o0 = (((size_t)((r0 >> 11) * HN + h) * TLEN) + (r0 & 2047)) * DD + d;
            const size_t o1 = (((size_t)((r1 >> 11) * HN + h) * TLEN) + (r1 & 2047)) * DD + d;
            *reinterpret_cast<uint32_t*>(oh + o0) =
                round2((acc[mt][nt][0] + b0) * scale, (acc[mt][nt][1] + b1) * scale);
            *reinterpret_cast<uint32_t*>(oh + o1) =
                round2((acc[mt][nt][2] + b0) * scale, (acc[mt][nt][3] + b1) * scale);
        }
    }
}

// ===========================================================================
// Projection GEMM (fp32 out, flat [M,N]).
// ===========================================================================
__global__ __launch_bounds__(256, 2)
void gemm_proj(const __half* __restrict__ Ar, const __half* __restrict__ Wr,
               const float* __restrict__ bias, float* __restrict__ out)
{
    extern __shared__ __align__(1024) char smem[];
    const uint32_t sbase = smem_u32(smem);
    const int m0 = blockIdx.y * 128;
    const int n0 = blockIdx.x * 128;

    float acc[2][8][4];
#pragma unroll
    for (int mt = 0; mt < 2; mt++)
#pragma unroll
        for (int nt = 0; nt < 8; nt++)
#pragma unroll
            for (int e = 0; e < 4; e++) acc[mt][nt][e] = 0.0f;

    gemm_mainloop(Ar, Wr, m0, n0, sbase, acc);

    const int lane = threadIdx.x & 31;
    const int wid  = threadIdx.x >> 5;
    const int m_off = (wid & 3) * 32;
    const int n_off = (wid >> 2) * 64;

#pragma unroll
    for (int mt = 0; mt < 2; mt++) {
#pragma unroll
        for (int nt = 0; nt < 8; nt++) {
            const int n  = n0 + n_off + nt * 8 + (lane & 3) * 2;
            const int r0 = m0 + m_off + mt * 16 + (lane >> 2);
            const int r1 = r0 + 8;
            const float b0 = bias[n], b1 = bias[n + 1];
            *reinterpret_cast<float2*>(out + (size_t)r0 * CDIM + n) =
                make_float2(acc[mt][nt][0] + b0, acc[mt][nt][1] + b1);
            *reinterpret_cast<float2*>(out + (size_t)r1 * CDIM + n) =
                make_float2(acc[mt][nt][2] + b0, acc[mt][nt][3] + b1);
        }
    }
}

// ===========================================================================
// HMMA flash attention (causal), fp16 1-term, zero-shift log2 softmax
// (R14 form): P = exp2(S) via ex2.approx.f16x2; l via ones-column MMA.
// CTA = 128 q x one (b,h), 256 threads, 4-stage KV ring, heavy first.
// ===========================================================================
#define AT_Q 0
#define AT_STAGE0 16384
#define AT_STAGE_BYTES 16384          // KH,VH each 8 KB
#define ATTN_SMEM (AT_STAGE0 + 4 * AT_STAGE_BYTES)   // 80 KB

__global__ __launch_bounds__(256, 2)
void flash_hmma(const __half* __restrict__ Qr,
                const __half* __restrict__ Kh, const __half* __restrict__ Vh,
                __half* __restrict__ Yr)
{
    extern __shared__ __align__(1024) char smem[];
    const uint32_t sbase = smem_u32(smem);

    const int tid  = threadIdx.x;
    const int lane = tid & 31;
    const int w    = tid >> 5;
    const int gid  = lane >> 2;
    const int tig  = lane & 3;
    const int bh = blockIdx.y;
    const int b  = bh >> 4;
    const int h  = bh & 15;
    const int bx = (int)gridDim.x - 1 - (int)blockIdx.x;   // heavy tiles first
    const int qbase = bx * 128;
    const int last = 2 * bx + 1;

    const size_t bh_off = (size_t)bh * TLEN * DD;

    const int a_row_l = ((lane >> 3) & 1) * 8 + (lane & 7);
    const int a_chunk = lane >> 4;
    const int b_row_l = ((lane >> 4) & 1) * 8 + (lane & 7);
    const int b_chunk = (lane >> 3) & 1;

    const uint32_t vone = (lane < 4) ? 0x3C003C00u : 0u;
    const uint32_t vfrag[2] = {vone, vone};

    const __half* kv_base[4];
    uint32_t kv_dst[4];
#pragma unroll
    for (int i = 0; i < 4; i++) {
        const int j = tid + i * 256;
        const int plane = j >> 9;           // 0:KH 1:VH
        const int r = (j >> 3) & 63;
        const int c = j & 7;
        const __half* sp = (plane == 0) ? Kh : Vh;
        kv_base[i] = sp + bh_off + (size_t)r * DD + c * 8;
        kv_dst[i]  = sbase + AT_STAGE0 +
                     (uint32_t)(plane * 8192 + r * 128 + ((c * 16) ^ ((r & 7) << 4)));
    }

    auto issue_KV = [&](int kt) {
        const int ke = kt * 64 * DD;
        const uint32_t boff = (uint32_t)((kt & 3) * AT_STAGE_BYTES);
#pragma unroll
        for (int i = 0; i < 4; i++)
            cp_async16(kv_dst[i] + boff, kv_base[i] + ke);
    };

    {
#pragma unroll
        for (int i = 0; i < 4; i++) {
            const int j = tid + i * 256;
            const int r = j >> 3;
            const int c = j & 7;
            const __half* src = Qr + bh_off + (size_t)(qbase + r) * DD + c * 8;
            const uint32_t dst = sbase + (uint32_t)(r * 128 + ((c * 16) ^ ((r & 7) << 4)));
            cp_async16(dst, src);
        }
    }
    issue_KV(0); CP_COMMIT();
    issue_KV(1); CP_COMMIT();
    if (2 <= last) { issue_KV(2); CP_COMMIT(); CP_WAIT(2); }
    else           { CP_WAIT(1); }
    __syncthreads();

    uint32_t qf[4][4];
#pragma unroll
    for (int ks = 0; ks < 4; ks++) {
        const int row = w * 16 + a_row_l;
        const uint32_t addr = (uint32_t)(row * 128) +
            (((uint32_t)(ks * 32 + a_chunk * 16)) ^ (((uint32_t)(row & 7)) << 4));
        ldsm4(qf[ks], sbase + AT_Q + addr);
    }

    float O[8][4];
#pragma unroll
    for (int nt = 0; nt < 8; nt++)
#pragma unroll
        for (int e = 0; e < 4; e++) O[nt][e] = 0.0f;
    float Ol[4] = {0.0f, 0.0f, 0.0f, 0.0f};

    const int q0 = qbase + w * 16 + gid;
    const int q1 = q0 + 8;

    for (int kt = 0; kt <= last; kt++) {
        const uint32_t stg = sbase + AT_STAGE0 + (uint32_t)((kt & 3) * AT_STAGE_BYTES);
        const uint32_t sKH = stg, sVH = stg + 8192;

        float S[8][4];
#pragma unroll
        for (int nt = 0; nt < 8; nt++)
#pragma unroll
            for (int e = 0; e < 4; e++) S[nt][e] = 0.0f;

#pragma unroll
        for (int ks = 0; ks < 4; ks++) {
            uint32_t kfh[4][4];
#pragma unroll
            for (int np = 0; np < 4; np++) {
                const int row = np * 16 + b_row_l;
                const uint32_t addr = (uint32_t)(row * 128) +
                    (((uint32_t)(ks * 32 + b_chunk * 16)) ^ (((uint32_t)(row & 7)) << 4));
                ldsm4(kfh[np], sKH + addr);
            }
#pragma unroll
            for (int np = 0; np < 4; np++) {
                mma16816(S[2 * np],     qf[ks], &kfh[np][0]);
                mma16816(S[2 * np + 1], qf[ks], &kfh[np][2]);
            }
        }

        if (kt >= 2 * bx) {
#pragma unroll
            for (int nt = 0; nt < 8; nt++) {
                const int k0 = kt * 64 + nt * 8 + 2 * tig;
                if (k0     > q0) S[nt][0] = -1e4f;
                if (k0 + 1 > q0) S[nt][1] = -1e4f;
                if (k0     > q1) S[nt][2] = -1e4f;
                if (k0 + 1 > q1) S[nt][3] = -1e4f;
            }
        }

        uint32_t pf[4][4];
#pragma unroll
        for (int ks = 0; ks < 4; ks++) {
            pf[ks][0] = ex2h2(round2(S[2 * ks][0],     S[2 * ks][1]));
            pf[ks][1] = ex2h2(round2(S[2 * ks][2],     S[2 * ks][3]));
            pf[ks][2] = ex2h2(round2(S[2 * ks + 1][0], S[2 * ks + 1][1]));
            pf[ks][3] = ex2h2(round2(S[2 * ks + 1][2], S[2 * ks + 1][3]));
        }

#pragma unroll
        for (int ks = 0; ks < 4; ks++) {
            uint32_t vfh[4][4];
#pragma unroll
            for (int db = 0; db < 4; db++) {
                const int row = ks * 16 + a_row_l;
                const uint32_t addr = (uint32_t)(row * 128) +
                    (((uint32_t)(db * 32 + a_chunk * 16)) ^ (((uint32_t)(row & 7)) << 4));
                ldsm4t(vfh[db], sVH + addr);
            }
#pragma unroll
            for (int db = 0; db < 4; db++) {
                mma16816(O[2 * db],     pf[ks], &vfh[db][0]);
                mma16816(O[2 * db + 1], pf[ks], &vfh[db][2]);
            }
            mma16816(Ol, pf[ks], vfrag);
        }

        if (kt == last) break;
        if (kt + 3 <= last) {
            issue_KV(kt + 3); CP_COMMIT();
            CP_WAIT(2);
        } else {
            CP_WAIT(0);
        }
        __syncthreads();
    }

    const float l0 = __shfl_sync(0xffffffffu, Ol[0], lane & ~3);
    const float l1 = __shfl_sync(0xffffffffu, Ol[2], lane & ~3);
    const float inv0 = 1.0f / l0;
    const float inv1 = 1.0f / l1;
    __half* y0 = Yr + ((size_t)b * TLEN + q0) * CDIM + h * 64;
    __half* y1 = Yr + ((size_t)b * TLEN + q1) * CDIM + h * 64;
#pragma unroll
    for (int nt = 0; nt < 8; nt++) {
        const int col = nt * 8 + 2 * tig;
        *reinterpret_cast<uint32_t*>(y0 + col) = round2(O[nt][0] * inv0, O[nt][1] * inv0);
        *reinterpret_cast<uint32_t*>(y1 + col) = round2(O[nt][2] * inv1, O[nt][3] * inv1);
    }
}

// ---------------------------------------------------------------------------
extern "C" void kernel_launch(void* const* d_in, const int* in_sizes, int n_in,
                              void* d_out, int out_size)
{
    const float* x  = (const float*)d_in[0];
    const float* Wq = (const float*)d_in[1];
    const float* bq = (const float*)d_in[2];
    const float* Wk = (const float*)d_in[3];
    const float* bk = (const float*)d_in[4];
    const float* Wv = (const float*)d_in[5];
    const float* bv = (const float*)d_in[6];
    const float* Wp = (const float*)d_in[7];
    const float* bp = (const float*)d_in[8];
    float* out = (float*)d_out;

    __half *xr, *wq, *wk, *wv, *wp;
    __half *qr, *kh, *vh, *yr;
    cudaGetSymbolAddress((void**)&xr, g_xr);
    cudaGetSymbolAddress((void**)&wq, g_wq); cudaGetSymbolAddress((void**)&wk, g_wk);
    cudaGetSymbolAddress((void**)&wv, g_wv); cudaGetSymbolAddress((void**)&wp, g_wp);
    cudaGetSymbolAddress((void**)&qr, g_qr);
    cudaGetSymbolAddress((void**)&kh, g_kh); cudaGetSymbolAddress((void**)&vh, g_vh);
    cudaGetSymbolAddress((void**)&yr, g_yr);

    cudaFuncSetAttribute(gemm_qkv,  cudaFuncAttributeMaxDynamicSharedMemorySize, GEMM_SMEM);
    cudaFuncSetAttribute(gemm_proj, cudaFuncAttributeMaxDynamicSharedMemorySize, GEMM_SMEM);
    cudaFuncSetAttribute(flash_hmma, cudaFuncAttributeMaxDynamicSharedMemorySize, ATTN_SMEM);

    PrepArgs pa;
    pa.x = x; pa.wq = Wq; pa.wk = Wk; pa.wv = Wv; pa.wp = Wp;
    pa.xr = xr; pa.dq = wq; pa.dk = wk; pa.dv = wv; pa.dp = wp;
    round_all<<<12288, 256>>>(pa);   // 8192 x-blocks + 4*1024 W-blocks

    QKVArgs args;
    args.W0 = wq; args.W1 = wk; args.W2 = wv;
    args.b0 = bq; args.b1 = bk; args.b2 = bv;
    args.o0 = qr; args.o1 = kh; args.o2 = vh;

    dim3 qkv_grid(3 * CDIM / 128, MROWS / 128);   // (24, 64)
    gemm_qkv<<<qkv_grid, 256, GEMM_SMEM>>>(xr, args);

    dim3 attn_grid(TLEN / 128, BSZ * HN);         // (16, 64)
    flash_hmma<<<attn_grid, 256, ATTN_SMEM>>>(qr, kh, vh, yr);

    dim3 proj_grid(CDIM / 128, MROWS / 128);      // (8, 64)
    gemm_proj<<<proj_grid, 256, GEMM_SMEM>>>(yr, wp, bp, out);
}